// round 2
// baseline (speedup 1.0000x reference)
#include <cuda_runtime.h>
#include <math.h>

#define NN   10000
#define NE   320000
#define BB   8
#define TTI  12
#define CIN  2
#define HH   64
#define NBT  (NN*BB*TTI)       /* 960000 positions */
#define TOT  (NBT*HH)          /* 61,440,000 floats */
#define FDIM (BB*TTI*HH)       /* 6144 */
#define F4   (FDIM/4)          /* 1536 */

// ---------------- scratch (device globals; no allocs allowed) ----------------
__device__ __align__(16) float g_T0[TOT];
__device__ __align__(16) float g_Y1[TOT];
__device__ __align__(16) float g_Y2[TOT];
__device__ __align__(16) float g_S [TOT];
__device__ float g_degw[NN];
__device__ int   g_cnt[NN];
__device__ float g_dis[NN];
__device__ int   g_rowptr[NN+1];
__device__ int   g_cursor[NN];
__device__ int   g_colidx[NE];
__device__ float g_ew[NE];

// ---------------- CSR build ----------------
__global__ void init_kernel() {
    int i = blockIdx.x*256 + threadIdx.x;
    if (i < NN) { g_degw[i] = 0.f; g_cnt[i] = 0; }
}

__global__ void hist_kernel(const int* __restrict__ row, const float* __restrict__ ew) {
    int e = blockIdx.x*256 + threadIdx.x;
    if (e < NE) {
        int r = row[e];
        atomicAdd(&g_degw[r], ew[e]);
        atomicAdd(&g_cnt[r], 1);
    }
}

__global__ void dis_kernel() {
    int i = blockIdx.x*256 + threadIdx.x;
    if (i < NN) {
        float d = g_degw[i];
        g_dis[i] = d > 0.f ? rsqrtf(d) : 0.f;
    }
}

// single-block exclusive scan of g_cnt -> g_rowptr, g_cursor
__global__ void scan_kernel() {
    __shared__ int s[1024];
    int tid = threadIdx.x;
    int lo = tid * 10;
    int sum = 0;
    for (int r = lo; r < lo+10 && r < NN; r++) sum += g_cnt[r];
    s[tid] = sum;
    __syncthreads();
    for (int off = 1; off < 1024; off <<= 1) {
        int v = (tid >= off) ? s[tid-off] : 0;
        __syncthreads();
        s[tid] += v;
        __syncthreads();
    }
    int run = s[tid] - sum;   // exclusive prefix
    for (int r = lo; r < lo+10 && r < NN; r++) {
        g_rowptr[r] = run;
        g_cursor[r] = run;
        run += g_cnt[r];
    }
    if (tid == 1023) g_rowptr[NN] = s[1023];
}

__global__ void scatter_kernel(const int* __restrict__ row, const int* __restrict__ col,
                               const float* __restrict__ ew) {
    int e = blockIdx.x*256 + threadIdx.x;
    if (e < NE) {
        int r = row[e], c = col[e];
        int p = atomicAdd(&g_cursor[r], 1);
        g_colidx[p] = c;
        g_ew[p] = -g_dis[r] * ew[e] * g_dis[c];   // L_hat weight (sym norm, lambda_max=2)
    }
}

// ---------------- temporal conv 1:  X[B,T,N,C] -> g_T0[N,B,T,H] ----------------
__global__ __launch_bounds__(256) void tconv1_kernel(const float* __restrict__ X,
        const float* __restrict__ w1, const float* __restrict__ b1,
        const float* __restrict__ w2, const float* __restrict__ b2,
        const float* __restrict__ w3, const float* __restrict__ b3) {
    __shared__ float sw[3][HH*CIN*3];
    __shared__ float sb[3][HH];
    int tid = threadIdx.y*64 + threadIdx.x;
    for (int i = tid; i < HH*CIN*3; i += 256) { sw[0][i]=w1[i]; sw[1][i]=w2[i]; sw[2][i]=w3[i]; }
    if (tid < HH) { sb[0][tid]=b1[tid]; sb[1][tid]=b2[tid]; sb[2][tid]=b3[tid]; }
    __syncthreads();

    int pos = blockIdx.x*4 + threadIdx.y;        // pos = (n*B + b)*T + t
    int h = threadIdx.x;
    int t  = pos % TTI;
    int nb = pos / TTI;
    int b  = nb % BB;
    int n  = nb / BB;

    float xv[3][CIN];
#pragma unroll
    for (int k = 0; k < 3; k++) {
        int t2 = t + k - 1;
        if (t2 >= 0 && t2 < TTI) {
#pragma unroll
            for (int c = 0; c < CIN; c++)
                xv[k][c] = X[((b*TTI + t2)*NN + n)*CIN + c];
        } else {
            xv[k][0] = 0.f; xv[k][1] = 0.f;
        }
    }
    float p = sb[0][h], q = sb[1][h], r = sb[2][h];
#pragma unroll
    for (int c = 0; c < CIN; c++)
#pragma unroll
        for (int k = 0; k < 3; k++) {
            float v = xv[k][c];
            p += v * sw[0][h*6 + c*3 + k];
            q += v * sw[1][h*6 + c*3 + k];
            r += v * sw[2][h*6 + c*3 + k];
        }
    float sg = 1.f / (1.f + expf(-q));
    g_T0[pos*HH + h] = fmaxf(p*sg + r, 0.f);
}

// ---------------- graph prop: y[n,:] = sum_e w[e] * x[col[e],:] ----------------
// grid (NN, 6): blockIdx.x fastest -> all nodes of one 1024-float feature chunk
// run together => 41MB L2-resident working set per chunk.
__global__ __launch_bounds__(256) void prop_kernel(int mode) {
    const float4* __restrict__ x = (const float4*)(mode ? g_Y1 : g_T0);
    float4* __restrict__ y       = (float4*)(mode ? g_Y2 : g_Y1);
    int n = blockIdx.x;
    int f = blockIdx.y*256 + threadIdx.x;     // float4 index in [0,1536)
    int beg = g_rowptr[n], end = g_rowptr[n+1];
    float4 acc = make_float4(0.f, 0.f, 0.f, 0.f);
    int e = beg;
    for (; e + 4 <= end; e += 4) {
        int   c0 = g_colidx[e],   c1 = g_colidx[e+1], c2 = g_colidx[e+2], c3 = g_colidx[e+3];
        float w0 = g_ew[e],       w1 = g_ew[e+1],     w2 = g_ew[e+2],     w3 = g_ew[e+3];
        float4 v0 = x[c0*F4 + f], v1 = x[c1*F4 + f],  v2 = x[c2*F4 + f],  v3 = x[c3*F4 + f];
        acc.x += w0*v0.x + w1*v1.x + w2*v2.x + w3*v3.x;
        acc.y += w0*v0.y + w1*v1.y + w2*v2.y + w3*v3.y;
        acc.z += w0*v0.z + w1*v1.z + w2*v2.z + w3*v3.z;
        acc.w += w0*v0.w + w1*v1.w + w2*v2.w + w3*v3.w;
    }
    for (; e < end; e++) {
        int c = g_colidx[e]; float w = g_ew[e];
        float4 v = x[c*F4 + f];
        acc.x += w*v.x; acc.y += w*v.y; acc.z += w*v.z; acc.w += w*v.w;
    }
    y[n*F4 + f] = acc;
}

// ---------------- cheb combine: S = relu(T0@W0 + Y1@W1 + (2*Y2-T0)@W2 + b) ----
// block = 64 positions, dynamic smem: Ws[3][64*65] + xs[3][64*64] + bias
#define CMB_SMEM_F (3*64*65 + 3*64*64 + 64)
__global__ __launch_bounds__(256) void combine_kernel(const float* __restrict__ Wc,
                                                      const float* __restrict__ bias) {
    extern __shared__ float sm[];
    float* Ws = sm;                         // [m][i*65 + h]
    float* xs = sm + 3*64*65;               // [m][p*64 + i]
    float* bs = sm + 3*64*65 + 3*64*64;
    int tid = threadIdx.x;
    for (int idx = tid; idx < 3*64*64; idx += 256) {
        int m = idx >> 12; int r = idx & 4095; int i = r >> 6; int h = r & 63;
        Ws[m*4160 + i*65 + h] = Wc[idx];
    }
    if (tid < 64) bs[tid] = bias[tid];
    int base = blockIdx.x * 4096;           // 64 positions * 64
    for (int idx = tid; idx < 4096; idx += 256) {
        float a = g_T0[base+idx], u = g_Y1[base+idx], v = g_Y2[base+idx];
        xs[idx]        = a;
        xs[4096 + idx] = u;
        xs[8192 + idx] = 2.f*v - a;
    }
    __syncthreads();

    int og = tid & 31, pg = tid >> 5;       // warp = fixed pg -> x loads uniform
    for (int chunk = 0; chunk < 2; chunk++) {
        int p0 = (chunk*8 + pg) * 4;
        float acc0[4], acc1[4];
        float bz0 = bs[og], bz1 = bs[og+32];
#pragma unroll
        for (int pp = 0; pp < 4; pp++) { acc0[pp] = bz0; acc1[pp] = bz1; }
        const float* x0 = xs + p0*64;
#pragma unroll 4
        for (int i = 0; i < 64; i++) {
            float w00 = Ws[i*65+og],        w01 = Ws[i*65+og+32];
            float w10 = Ws[4160+i*65+og],   w11 = Ws[4160+i*65+og+32];
            float w20 = Ws[8320+i*65+og],   w21 = Ws[8320+i*65+og+32];
#pragma unroll
            for (int pp = 0; pp < 4; pp++) {
                float a0 = x0[pp*64 + i];
                float a1 = x0[4096 + pp*64 + i];
                float a2 = x0[8192 + pp*64 + i];
                acc0[pp] += a0*w00; acc0[pp] += a1*w10; acc0[pp] += a2*w20;
                acc1[pp] += a0*w01; acc1[pp] += a1*w11; acc1[pp] += a2*w21;
            }
        }
#pragma unroll
        for (int pp = 0; pp < 4; pp++) {
            g_S[base + (p0+pp)*64 + og]      = fmaxf(acc0[pp], 0.f);
            g_S[base + (p0+pp)*64 + og + 32] = fmaxf(acc1[pp], 0.f);
        }
    }
}

// ---------------- temporal conv 2: g_S[N,B,T,H] -> out[B,T,N,H] ---------------
// block = 16 (n,b) pairs (192 positions). All 9 weight mats + padded x in smem.
#define T2_SMEM_F (3*192*65 + 16*14*64 + 192)
__global__ __launch_bounds__(256) void tconv2_kernel(
        const float* __restrict__ w1, const float* __restrict__ b1,
        const float* __restrict__ w2, const float* __restrict__ b2,
        const float* __restrict__ w3, const float* __restrict__ b3,
        float* __restrict__ out) {
    extern __shared__ float sm[];
    float* Wt = sm;                         // [m][(c*3+k)*65 + o]
    float* xs = sm + 3*192*65;              // [pair][tt*64 + c], tt=0..13 (zero-padded ends)
    float* bs = sm + 3*192*65 + 16*14*64;
    int tid = threadIdx.x;
    for (int idx = tid; idx < 64*192; idx += 256) {
        int o = idx / 192, j = idx - o*192;   // original layout: w[o*192 + c*3 + k]
        Wt[j*65 + o]         = w1[idx];
        Wt[12480 + j*65 + o] = w2[idx];
        Wt[24960 + j*65 + o] = w3[idx];
    }
    if (tid < 64) { bs[tid]=b1[tid]; bs[64+tid]=b2[tid]; bs[128+tid]=b3[tid]; }
    int nb0 = blockIdx.x * 16;
    for (int idx = tid; idx < 16*TTI*64; idx += 256) {
        int pair = idx / 768; int r = idx - pair*768; int t = r >> 6; int c = r & 63;
        xs[pair*896 + (t+1)*64 + c] = g_S[(nb0+pair)*768 + t*64 + c];
    }
    for (int idx = tid; idx < 16*128; idx += 256) {
        int pair = idx >> 7; int r = idx & 127;
        int t = (r >> 6) ? 13 : 0; int c = r & 63;
        xs[pair*896 + t*64 + c] = 0.f;
    }
    __syncthreads();

    int og = tid & 31, pg = tid >> 5;
    for (int chunk = 0; chunk < 6; chunk++) {
        float aP0[4], aP1[4], aQ0[4], aQ1[4], aR0[4], aR1[4];
        float bp0 = bs[og], bp1 = bs[og+32];
        float bq0 = bs[64+og], bq1 = bs[64+og+32];
        float br0 = bs[128+og], br1 = bs[128+og+32];
        int xbase[4], pidx[4];
#pragma unroll
        for (int pp = 0; pp < 4; pp++) {
            aP0[pp]=bp0; aP1[pp]=bp1; aQ0[pp]=bq0; aQ1[pp]=bq1; aR0[pp]=br0; aR1[pp]=br1;
            int p = chunk*32 + pg*4 + pp;          // 0..191
            int pair = p / 12, t = p - pair*12;
            xbase[pp] = pair*896 + t*64;           // tap k reads +k*64 (tt = t+k)
            pidx[pp] = p;
        }
        for (int k = 0; k < 3; k++) {
#pragma unroll 4
            for (int c = 0; c < 64; c++) {
                int j = c*3 + k;
                float wp0 = Wt[j*65+og],        wp1 = Wt[j*65+og+32];
                float wq0 = Wt[12480+j*65+og],  wq1 = Wt[12480+j*65+og+32];
                float wr0 = Wt[24960+j*65+og],  wr1 = Wt[24960+j*65+og+32];
#pragma unroll
                for (int pp = 0; pp < 4; pp++) {
                    float xv = xs[xbase[pp] + k*64 + c];
                    aP0[pp] += xv*wp0; aP1[pp] += xv*wp1;
                    aQ0[pp] += xv*wq0; aQ1[pp] += xv*wq1;
                    aR0[pp] += xv*wr0; aR1[pp] += xv*wr1;
                }
            }
        }
#pragma unroll
        for (int pp = 0; pp < 4; pp++) {
            int p = pidx[pp]; int pair = p/12, t = p - pair*12;
            int nb = nb0 + pair; int n = nb >> 3; int b = nb & 7;
            int obase = ((b*TTI + t)*NN + n)*64;
            float sg0 = 1.f/(1.f + expf(-aQ0[pp]));
            float sg1 = 1.f/(1.f + expf(-aQ1[pp]));
            out[obase + og]      = fmaxf(aP0[pp]*sg0 + aR0[pp], 0.f);
            out[obase + og + 32] = fmaxf(aP1[pp]*sg1 + aR1[pp], 0.f);
        }
    }
}

// ---------------- launch ----------------
extern "C" void kernel_launch(void* const* d_in, const int* in_sizes, int n_in,
                              void* d_out, int out_size) {
    const float* X    = (const float*)d_in[0];
    const int*   ei   = (const int*)  d_in[1];
    const float* ew   = (const float*)d_in[2];
    const float* t1w1 = (const float*)d_in[3];  const float* t1b1 = (const float*)d_in[4];
    const float* t1w2 = (const float*)d_in[5];  const float* t1b2 = (const float*)d_in[6];
    const float* t1w3 = (const float*)d_in[7];  const float* t1b3 = (const float*)d_in[8];
    const float* cW   = (const float*)d_in[9];  const float* cb   = (const float*)d_in[10];
    const float* t2w1 = (const float*)d_in[11]; const float* t2b1 = (const float*)d_in[12];
    const float* t2w2 = (const float*)d_in[13]; const float* t2b2 = (const float*)d_in[14];
    const float* t2w3 = (const float*)d_in[15]; const float* t2b3 = (const float*)d_in[16];
    float* out = (float*)d_out;
    const int* row = ei;
    const int* col = ei + NE;

    cudaFuncSetAttribute(combine_kernel, cudaFuncAttributeMaxDynamicSharedMemorySize,
                         CMB_SMEM_F * (int)sizeof(float));
    cudaFuncSetAttribute(tconv2_kernel, cudaFuncAttributeMaxDynamicSharedMemorySize,
                         T2_SMEM_F * (int)sizeof(float));

    init_kernel   <<<(NN+255)/256, 256>>>();
    hist_kernel   <<<(NE+255)/256, 256>>>(row, ew);
    dis_kernel    <<<(NN+255)/256, 256>>>();
    scan_kernel   <<<1, 1024>>>();
    scatter_kernel<<<(NE+255)/256, 256>>>(row, col, ew);

    tconv1_kernel <<<NBT/4, dim3(64,4)>>>(X, t1w1,t1b1, t1w2,t1b2, t1w3,t1b3);

    prop_kernel   <<<dim3(NN, 6), 256>>>(0);   // Y1 = L * T0
    prop_kernel   <<<dim3(NN, 6), 256>>>(1);   // Y2 = L * Y1

    combine_kernel<<<NBT/64, 256, CMB_SMEM_F*(int)sizeof(float)>>>(cW, cb);

    tconv2_kernel <<<NN*BB/16, 256, T2_SMEM_F*(int)sizeof(float)>>>(
        t2w1,t2b1, t2w2,t2b2, t2w3,t2b3, out);
}